// round 1
// baseline (speedup 1.0000x reference)
#include <cuda_runtime.h>
#include <cuda_bf16.h>
#include <math.h>

// ---------------- problem constants ----------------
#define BATCH     2
#define SEQ       2048
#define TTOT      (BATCH*SEQ)        // 4096
#define DMODEL    1024
#define DINNER    2048
#define DHEAD     64
#define NHEADS    32
#define DSTATE    64
#define DCONV     4
#define CONVDIM   (DINNER + 2*DSTATE)            // 2176
#define DINPROJ   (2*DINNER + 2*DSTATE + NHEADS) // 4256
#define NLAYERS   4
#define EPSV      1e-5f

// ---------------- scratch (device globals; no allocs allowed) ----------------
__device__ float g_xn[(size_t)TTOT * DMODEL];       // rmsnormed input
__device__ float g_zxbcdt[(size_t)TTOT * DINPROJ];  // in_proj output
__device__ float g_xconv[(size_t)TTOT * CONVDIM];   // silu(conv(xBC))
__device__ float g_dt[(size_t)TTOT * NHEADS];       // softplus(dt + bias)
__device__ float g_y[(size_t)TTOT * DINNER];        // SSD output (+ D*X)
__device__ float g_g[(size_t)TTOT * DINNER];        // gated + normed

// ---------------- rmsnorm over a row ----------------
__global__ void rmsnorm_kernel(const float* __restrict__ x,
                               const float* __restrict__ w,
                               float* __restrict__ o, int D)
{
    int t = blockIdx.x;
    const float* xr = x + (size_t)t * D;
    float lsum = 0.f;
    for (int i = threadIdx.x; i < D; i += blockDim.x) {
        float v = xr[i];
        lsum += v * v;
    }
    // block reduce
    __shared__ float wsum[8];
    int lane = threadIdx.x & 31, wid = threadIdx.x >> 5;
    #pragma unroll
    for (int off = 16; off > 0; off >>= 1)
        lsum += __shfl_xor_sync(0xffffffffu, lsum, off);
    if (lane == 0) wsum[wid] = lsum;
    __syncthreads();
    __shared__ float s_rs;
    if (threadIdx.x == 0) {
        float tot = 0.f;
        int nw = blockDim.x >> 5;
        for (int i = 0; i < nw; i++) tot += wsum[i];
        s_rs = rsqrtf(tot / (float)D + EPSV);
    }
    __syncthreads();
    float rs = s_rs;
    float* orow = o + (size_t)t * D;
    for (int i = threadIdx.x; i < D; i += blockDim.x)
        orow[i] = xr[i] * rs * w[i];
}

// ---------------- tiled NT GEMM: C[M,N] = A[M,K] @ B[N,K]^T (+C) ----------------
// BM=BN=128, BK=8, 256 threads, 8x8 per thread.
#define GBM 128
#define GBN 128
#define GBK 8
__global__ __launch_bounds__(256, 2)
void gemm_nt_kernel(const float* __restrict__ A, const float* __restrict__ B,
                    float* __restrict__ C, int M, int N, int K, int addC)
{
    __shared__ float As[GBK][GBM];
    __shared__ float Bs[GBK][GBN];

    int tid = threadIdx.x;
    int m0 = blockIdx.y * GBM;
    int n0 = blockIdx.x * GBN;
    int tr = tid >> 4;   // 0..15
    int tc = tid & 15;   // 0..15

    float acc[8][8];
    #pragma unroll
    for (int i = 0; i < 8; i++)
        #pragma unroll
        for (int j = 0; j < 8; j++) acc[i][j] = 0.f;

    int lrow  = tid >> 1;         // 0..127
    int lcol4 = (tid & 1) * 4;    // 0 or 4

    for (int k0 = 0; k0 < K; k0 += GBK) {
        // load A tile (transposed into smem)
        {
            int m = m0 + lrow;
            float4 v = make_float4(0.f, 0.f, 0.f, 0.f);
            if (m < M) v = *(const float4*)(A + (size_t)m * K + k0 + lcol4);
            As[lcol4 + 0][lrow] = v.x;
            As[lcol4 + 1][lrow] = v.y;
            As[lcol4 + 2][lrow] = v.z;
            As[lcol4 + 3][lrow] = v.w;
        }
        // load B tile
        {
            int n = n0 + lrow;
            float4 v = make_float4(0.f, 0.f, 0.f, 0.f);
            if (n < N) v = *(const float4*)(B + (size_t)n * K + k0 + lcol4);
            Bs[lcol4 + 0][lrow] = v.x;
            Bs[lcol4 + 1][lrow] = v.y;
            Bs[lcol4 + 2][lrow] = v.z;
            Bs[lcol4 + 3][lrow] = v.w;
        }
        __syncthreads();
        #pragma unroll
        for (int kk = 0; kk < GBK; kk++) {
            float4 a0 = *(const float4*)&As[kk][tr * 8];
            float4 a1 = *(const float4*)&As[kk][tr * 8 + 4];
            float4 b0 = *(const float4*)&Bs[kk][tc * 8];
            float4 b1 = *(const float4*)&Bs[kk][tc * 8 + 4];
            float av[8] = {a0.x, a0.y, a0.z, a0.w, a1.x, a1.y, a1.z, a1.w};
            float bv[8] = {b0.x, b0.y, b0.z, b0.w, b1.x, b1.y, b1.z, b1.w};
            #pragma unroll
            for (int i = 0; i < 8; i++)
                #pragma unroll
                for (int j = 0; j < 8; j++)
                    acc[i][j] = fmaf(av[i], bv[j], acc[i][j]);
        }
        __syncthreads();
    }

    #pragma unroll
    for (int i = 0; i < 8; i++) {
        int m = m0 + tr * 8 + i;
        if (m >= M) continue;
        #pragma unroll
        for (int j = 0; j < 8; j++) {
            int n = n0 + tc * 8 + j;
            if (n < N) {
                size_t idx = (size_t)m * N + n;
                C[idx] = addC ? (C[idx] + acc[i][j]) : acc[i][j];
            }
        }
    }
}

// ---------------- depthwise conv(4) + silu ----------------
__global__ void conv_silu_kernel(const float* __restrict__ zxbcdt,
                                 const float* __restrict__ cw,
                                 const float* __restrict__ cb,
                                 float* __restrict__ xconv)
{
    int idx = blockIdx.x * blockDim.x + threadIdx.x;
    if (idx >= TTOT * CONVDIM) return;
    int ch = idx % CONVDIM;
    int t  = idx / CONVDIM;
    int l  = t & (SEQ - 1);
    int b  = t >> 11;
    float acc = cb[ch];
    #pragma unroll
    for (int k = 0; k < DCONV; k++) {
        int ll = l + k - (DCONV - 1);
        if (ll >= 0)
            acc += zxbcdt[((size_t)(b * SEQ + ll)) * DINPROJ + DINNER + ch] * cw[ch * DCONV + k];
    }
    float s = acc / (1.f + __expf(-acc));   // silu
    xconv[(size_t)t * CONVDIM + ch] = s;
}

// ---------------- dt softplus ----------------
__global__ void dt_softplus_kernel(const float* __restrict__ zxbcdt,
                                   const float* __restrict__ dt_bias,
                                   float* __restrict__ dtout)
{
    int i = blockIdx.x * blockDim.x + threadIdx.x;
    if (i >= TTOT * NHEADS) return;
    int t = i >> 5;
    int h = i & 31;
    float v = zxbcdt[(size_t)t * DINPROJ + (DINPROJ - NHEADS) + h] + dt_bias[h];
    dtout[i] = (v > 20.f) ? v : log1pf(__expf(v));
}

// ---------------- SSD sequential scan: one block per (b,h) ----------------
// state[p][n], 256 threads: thread = (p, quad), quad owns 16 n values.
__global__ __launch_bounds__(256, 4)
void ssd_scan_kernel(const float* __restrict__ xconv,
                     const float* __restrict__ dt,
                     const float* __restrict__ A_log,
                     const float* __restrict__ Dvec,
                     float* __restrict__ y)
{
    int bh = blockIdx.x;
    int b = bh >> 5;
    int h = bh & 31;
    float A  = -__expf(A_log[h]);
    float Dh = Dvec[h];
    int tid  = threadIdx.x;
    int p    = tid >> 2;
    int quad = tid & 3;
    int n0   = quad * 16;

    __shared__ float sB[DSTATE], sC[DSTATE], sX[DHEAD];
    __shared__ float sdt;

    float s[16];
    #pragma unroll
    for (int j = 0; j < 16; j++) s[j] = 0.f;

    for (int l = 0; l < SEQ; l++) {
        int t = b * SEQ + l;
        const float* row = xconv + (size_t)t * CONVDIM;
        if (tid < 64)        sB[tid]        = row[DINNER + tid];
        else if (tid < 128)  sC[tid - 64]   = row[DINNER + DSTATE + (tid - 64)];
        else if (tid < 192)  sX[tid - 128]  = row[h * DHEAD + (tid - 128)];
        else if (tid == 192) sdt            = dt[(size_t)t * NHEADS + h];
        __syncthreads();

        float dts = sdt;
        float da  = __expf(dts * A);
        float xp  = sX[p] * dts;
        float acc = 0.f;
        #pragma unroll
        for (int j = 0; j < 16; j++) {
            s[j] = fmaf(da, s[j], xp * sB[n0 + j]);
            acc  = fmaf(sC[n0 + j], s[j], acc);
        }
        acc += __shfl_xor_sync(0xffffffffu, acc, 1);
        acc += __shfl_xor_sync(0xffffffffu, acc, 2);
        if (quad == 0)
            y[(size_t)t * DINNER + h * DHEAD + p] = acc + Dh * sX[p];
        __syncthreads();
    }
}

// ---------------- gate (y * silu(z)) + rmsnorm(gnorm_w) ----------------
__global__ void gate_norm_kernel(const float* __restrict__ zxbcdt,
                                 const float* __restrict__ y,
                                 const float* __restrict__ gw,
                                 float* __restrict__ g)
{
    int t = blockIdx.x;
    __shared__ float sv[DINNER];
    __shared__ float wsum[8];
    const float* zr = zxbcdt + (size_t)t * DINPROJ;
    const float* yr = y + (size_t)t * DINNER;
    float lsum = 0.f;
    for (int i = threadIdx.x; i < DINNER; i += blockDim.x) {
        float z = zr[i];
        float v = yr[i] * (z / (1.f + __expf(-z)));
        sv[i] = v;
        lsum += v * v;
    }
    int lane = threadIdx.x & 31, wid = threadIdx.x >> 5;
    #pragma unroll
    for (int off = 16; off > 0; off >>= 1)
        lsum += __shfl_xor_sync(0xffffffffu, lsum, off);
    if (lane == 0) wsum[wid] = lsum;
    __syncthreads();
    __shared__ float s_rs;
    if (threadIdx.x == 0) {
        float tot = 0.f;
        for (int i = 0; i < 8; i++) tot += wsum[i];
        s_rs = rsqrtf(tot / (float)DINNER + EPSV);
    }
    __syncthreads();
    float rs = s_rs;
    float* grow = g + (size_t)t * DINNER;
    for (int i = threadIdx.x; i < DINNER; i += blockDim.x)
        grow[i] = sv[i] * rs * gw[i];
}

// ---------------- host orchestration ----------------
extern "C" void kernel_launch(void* const* d_in, const int* in_sizes, int n_in,
                              void* d_out, int out_size)
{
    const float* x        = (const float*)d_in[0];
    const float* in_w     = (const float*)d_in[1];  // (4, 4256, 1024)
    const float* conv_w   = (const float*)d_in[2];  // (4, 2176, 4)
    const float* conv_b   = (const float*)d_in[3];  // (4, 2176)
    const float* dt_bias  = (const float*)d_in[4];  // (4, 32)
    const float* A_log    = (const float*)d_in[5];  // (4, 32)
    const float* Dvec     = (const float*)d_in[6];  // (4, 32)
    const float* gnorm_w  = (const float*)d_in[7];  // (4, 2048)
    const float* out_w    = (const float*)d_in[8];  // (4, 1024, 2048)
    const float* rms_w    = (const float*)d_in[9];  // (4, 1024)
    float* out = (float*)d_out;

    float *p_xn, *p_zx, *p_xc, *p_dt, *p_y, *p_g;
    cudaGetSymbolAddress((void**)&p_xn, g_xn);
    cudaGetSymbolAddress((void**)&p_zx, g_zxbcdt);
    cudaGetSymbolAddress((void**)&p_xc, g_xconv);
    cudaGetSymbolAddress((void**)&p_dt, g_dt);
    cudaGetSymbolAddress((void**)&p_y,  g_y);
    cudaGetSymbolAddress((void**)&p_g,  g_g);

    // residual stream lives in d_out
    cudaMemcpyAsync(out, x, (size_t)TTOT * DMODEL * sizeof(float),
                    cudaMemcpyDeviceToDevice);

    for (int layer = 0; layer < NLAYERS; layer++) {
        const float* lw_in   = in_w    + (size_t)layer * DINPROJ * DMODEL;
        const float* lw_cw   = conv_w  + (size_t)layer * CONVDIM * DCONV;
        const float* lw_cb   = conv_b  + (size_t)layer * CONVDIM;
        const float* lw_dtb  = dt_bias + (size_t)layer * NHEADS;
        const float* lw_Alog = A_log   + (size_t)layer * NHEADS;
        const float* lw_D    = Dvec    + (size_t)layer * NHEADS;
        const float* lw_gn   = gnorm_w + (size_t)layer * DINNER;
        const float* lw_out  = out_w   + (size_t)layer * DMODEL * DINNER;
        const float* lw_rms  = rms_w   + (size_t)layer * DMODEL;

        // 1. rmsnorm(x)
        rmsnorm_kernel<<<TTOT, 256>>>(out, lw_rms, p_xn, DMODEL);

        // 2. in_proj: zxbcdt = xn @ in_w^T
        {
            dim3 grid((DINPROJ + GBN - 1) / GBN, (TTOT + GBM - 1) / GBM);
            gemm_nt_kernel<<<grid, 256>>>(p_xn, lw_in, p_zx,
                                          TTOT, DINPROJ, DMODEL, 0);
        }

        // 3. conv + silu
        conv_silu_kernel<<<(TTOT * CONVDIM + 255) / 256, 256>>>(p_zx, lw_cw, lw_cb, p_xc);

        // 4. dt softplus
        dt_softplus_kernel<<<(TTOT * NHEADS + 255) / 256, 256>>>(p_zx, lw_dtb, p_dt);

        // 5. SSD scan (64 blocks: b*h)
        ssd_scan_kernel<<<BATCH * NHEADS, 256>>>(p_xc, p_dt, lw_Alog, lw_D, p_y);

        // 6. gate + group rmsnorm
        gate_norm_kernel<<<TTOT, 256>>>(p_zx, p_y, lw_gn, p_g);

        // 7. out_proj with residual add into d_out
        {
            dim3 grid((DMODEL + GBN - 1) / GBN, (TTOT + GBM - 1) / GBM);
            gemm_nt_kernel<<<grid, 256>>>(p_g, lw_out, out,
                                          TTOT, DMODEL, DINNER, 1);
        }
    }
}

// round 2
// speedup vs baseline: 2.1709x; 2.1709x over previous
#include <cuda_runtime.h>
#include <cuda_bf16.h>
#include <math.h>
#include <stdint.h>

// ---------------- problem constants ----------------
#define BATCH     2
#define SEQ       2048
#define TTOT      (BATCH*SEQ)        // 4096
#define DMODEL    1024
#define DINNER    2048
#define DHEAD     64
#define NHEADS    32
#define DSTATE    64
#define DCONV     4
#define CONVDIM   (DINNER + 2*DSTATE)            // 2176
#define DINPROJ   (2*DINNER + 2*DSTATE + NHEADS) // 4256
#define NLAYERS   4
#define EPSV      1e-5f

#define CHL       128                 // scan chunk length
#define NCH       (SEQ/CHL)           // 16 chunks per sequence

// ---------------- scratch (device globals; no allocs allowed) ----------------
__device__ float g_xn[(size_t)TTOT * DMODEL];       // rmsnormed input
__device__ float g_zxbcdt[(size_t)TTOT * DINPROJ];  // in_proj output
__device__ float g_xconv[(size_t)TTOT * CONVDIM];   // silu(conv(xBC))
__device__ float g_dt[(size_t)TTOT * NHEADS];       // softplus(dt + bias)
__device__ float g_y[(size_t)TTOT * DINNER];        // SSD output (+ D*X)
__device__ float g_g[(size_t)TTOT * DINNER];        // gated + normed
// split-bf16 operand buffers (max sizes across both GEMMs)
__device__ __nv_bfloat16 g_asp[(size_t)TTOT * 3 * DINNER];   // 4096 x 6144
__device__ __nv_bfloat16 g_bsp[(size_t)DINPROJ * 3 * DMODEL];// 4256 x 3072 (>=1024x6144)
// chunked-scan buffers
__device__ float g_Sloc[(size_t)BATCH*NHEADS*NCH * DHEAD * DSTATE];
__device__ float g_Sin [(size_t)BATCH*NHEADS*NCH * DHEAD * DSTATE];
__device__ float g_cumdt[(size_t)TTOT * NHEADS];    // inclusive cumsum of dt within chunk

// ---------------- rmsnorm over a row ----------------
__global__ void rmsnorm_kernel(const float* __restrict__ x,
                               const float* __restrict__ w,
                               float* __restrict__ o, int D)
{
    int t = blockIdx.x;
    const float* xr = x + (size_t)t * D;
    float lsum = 0.f;
    for (int i = threadIdx.x; i < D; i += blockDim.x) {
        float v = xr[i];
        lsum += v * v;
    }
    __shared__ float wsum[8];
    int lane = threadIdx.x & 31, wid = threadIdx.x >> 5;
    #pragma unroll
    for (int off = 16; off > 0; off >>= 1)
        lsum += __shfl_xor_sync(0xffffffffu, lsum, off);
    if (lane == 0) wsum[wid] = lsum;
    __syncthreads();
    __shared__ float s_rs;
    if (threadIdx.x == 0) {
        float tot = 0.f;
        int nw = blockDim.x >> 5;
        for (int i = 0; i < nw; i++) tot += wsum[i];
        s_rs = rsqrtf(tot / (float)D + EPSV);
    }
    __syncthreads();
    float rs = s_rs;
    float* orow = o + (size_t)t * D;
    for (int i = threadIdx.x; i < D; i += blockDim.x)
        orow[i] = xr[i] * rs * w[i];
}

// ---------------- split fp32 -> [hi, ?, ?] bf16 triplet along K ----------------
// mode 0 (A operand): [hi, lo, hi]; mode 1 (B operand): [hi, hi, lo]
// Sum over 3K of A'*B' = hi*hi + lo*hi + hi*lo  (error ~1e-5 relative)
__global__ void split_kernel(const float* __restrict__ X, __nv_bfloat16* __restrict__ O,
                             int rows, int K, int mode)
{
    int i = blockIdx.x * blockDim.x + threadIdx.x;
    if (i >= rows * K) return;
    int r = i / K, k = i % K;
    float x = X[i];
    __nv_bfloat16 hi = __float2bfloat16(x);
    __nv_bfloat16 lo = __float2bfloat16(x - __bfloat162float(hi));
    size_t base = (size_t)r * (3 * K) + k;
    O[base]         = hi;
    O[base + K]     = mode ? hi : lo;
    O[base + 2 * K] = mode ? lo : hi;
}

// ---------------- bf16 tensor-core NT GEMM: C[M,N] = A[M,K] @ B[N,K]^T (+C) ----
#define BM 128
#define BN 128
#define BK 32
#define PADH 8

__device__ __forceinline__ void gemm_issue_tile(
    const __nv_bfloat16* __restrict__ A, const __nv_bfloat16* __restrict__ B,
    int N, int K, int m0, int n0, int kbase,
    __nv_bfloat16 (*As)[BK + PADH], __nv_bfloat16 (*Bs)[BK + PADH], int tid)
{
    #pragma unroll
    for (int it = 0; it < 2; it++) {
        int id  = tid + it * 256;       // 0..511
        int row = id >> 2;              // 0..127
        int col = (id & 3) * 8;         // 0,8,16,24
        // A tile (M rows always in range for our shapes)
        {
            uint32_t saddr = (uint32_t)__cvta_generic_to_shared(&As[row][col]);
            const void* g = A + (size_t)(m0 + row) * K + kbase + col;
            asm volatile("cp.async.cg.shared.global [%0], [%1], 16;"
                         :: "r"(saddr), "l"(g));
        }
        // B tile (N may be ragged)
        {
            uint32_t saddr = (uint32_t)__cvta_generic_to_shared(&Bs[row][col]);
            int valid = (n0 + row) < N;
            const void* g = B + (valid ? ((size_t)(n0 + row) * K + kbase + col) : 0);
            int sz = valid ? 16 : 0;
            asm volatile("cp.async.cg.shared.global [%0], [%1], 16, %2;"
                         :: "r"(saddr), "l"(g), "r"(sz));
        }
    }
    asm volatile("cp.async.commit_group;");
}

__global__ __launch_bounds__(256, 2)
void gemm_bf16_nt(const __nv_bfloat16* __restrict__ A, const __nv_bfloat16* __restrict__ B,
                  float* __restrict__ C, int M, int N, int K, int addC)
{
    __shared__ __align__(16) __nv_bfloat16 As[2][BM][BK + PADH];
    __shared__ __align__(16) __nv_bfloat16 Bs[2][BN][BK + PADH];

    int tid  = threadIdx.x;
    int lane = tid & 31;
    int wid  = tid >> 5;
    int m0 = blockIdx.y * BM;
    int n0 = blockIdx.x * BN;
    int wm = (wid & 1) * 64;      // warp m offset within tile
    int wn = (wid >> 1) * 32;     // warp n offset within tile

    float acc[4][4][4];
    #pragma unroll
    for (int a = 0; a < 4; a++)
        #pragma unroll
        for (int b = 0; b < 4; b++)
            #pragma unroll
            for (int c = 0; c < 4; c++) acc[a][b][c] = 0.f;

    int NT = K / BK;
    gemm_issue_tile(A, B, N, K, m0, n0, 0, As[0], Bs[0], tid);

    for (int kt = 0; kt < NT; kt++) {
        asm volatile("cp.async.wait_group 0;");
        __syncthreads();
        if (kt + 1 < NT)
            gemm_issue_tile(A, B, N, K, m0, n0, (kt + 1) * BK,
                            As[(kt + 1) & 1], Bs[(kt + 1) & 1], tid);
        int st = kt & 1;

        #pragma unroll
        for (int ks = 0; ks < 2; ks++) {
            uint32_t af[4][4];
            uint32_t bf[4][2];
            #pragma unroll
            for (int mi = 0; mi < 4; mi++) {
                uint32_t addr = (uint32_t)__cvta_generic_to_shared(
                    &As[st][wm + mi * 16 + (lane & 15)][ks * 16 + (lane >> 4) * 8]);
                asm volatile("ldmatrix.sync.aligned.m8n8.x4.shared.b16 {%0,%1,%2,%3}, [%4];"
                             : "=r"(af[mi][0]), "=r"(af[mi][1]),
                               "=r"(af[mi][2]), "=r"(af[mi][3])
                             : "r"(addr));
            }
            #pragma unroll
            for (int nj = 0; nj < 4; nj++) {
                uint32_t addr = (uint32_t)__cvta_generic_to_shared(
                    &Bs[st][wn + nj * 8 + (lane & 7)][ks * 16 + ((lane >> 3) & 1) * 8]);
                asm volatile("ldmatrix.sync.aligned.m8n8.x2.shared.b16 {%0,%1}, [%2];"
                             : "=r"(bf[nj][0]), "=r"(bf[nj][1])
                             : "r"(addr));
            }
            #pragma unroll
            for (int mi = 0; mi < 4; mi++)
                #pragma unroll
                for (int nj = 0; nj < 4; nj++)
                    asm volatile(
                        "mma.sync.aligned.m16n8k16.row.col.f32.bf16.bf16.f32 "
                        "{%0,%1,%2,%3}, {%4,%5,%6,%7}, {%8,%9}, {%0,%1,%2,%3};"
                        : "+f"(acc[mi][nj][0]), "+f"(acc[mi][nj][1]),
                          "+f"(acc[mi][nj][2]), "+f"(acc[mi][nj][3])
                        : "r"(af[mi][0]), "r"(af[mi][1]),
                          "r"(af[mi][2]), "r"(af[mi][3]),
                          "r"(bf[nj][0]), "r"(bf[nj][1]));
        }
        __syncthreads();
    }

    // epilogue: d0,d1 at (row, col..col+1), d2,d3 at (row+8, col..col+1)
    #pragma unroll
    for (int mi = 0; mi < 4; mi++) {
        int r0 = m0 + wm + mi * 16 + (lane >> 2);
        #pragma unroll
        for (int nj = 0; nj < 4; nj++) {
            int c0 = n0 + wn + nj * 8 + (lane & 3) * 2;
            if (c0 < N) {
                float* p0 = C + (size_t)r0 * N + c0;
                float* p1 = C + (size_t)(r0 + 8) * N + c0;
                if (addC) {
                    p0[0] += acc[mi][nj][0];  p0[1] += acc[mi][nj][1];
                    p1[0] += acc[mi][nj][2];  p1[1] += acc[mi][nj][3];
                } else {
                    p0[0] = acc[mi][nj][0];   p0[1] = acc[mi][nj][1];
                    p1[0] = acc[mi][nj][2];   p1[1] = acc[mi][nj][3];
                }
            }
        }
    }
}

// ---------------- depthwise conv(4) + silu ----------------
__global__ void conv_silu_kernel(const float* __restrict__ zxbcdt,
                                 const float* __restrict__ cw,
                                 const float* __restrict__ cb,
                                 float* __restrict__ xconv)
{
    int idx = blockIdx.x * blockDim.x + threadIdx.x;
    if (idx >= TTOT * CONVDIM) return;
    int ch = idx % CONVDIM;
    int t  = idx / CONVDIM;
    int l  = t & (SEQ - 1);
    int b  = t >> 11;
    float acc = cb[ch];
    #pragma unroll
    for (int k = 0; k < DCONV; k++) {
        int ll = l + k - (DCONV - 1);
        if (ll >= 0)
            acc += zxbcdt[((size_t)(b * SEQ + ll)) * DINPROJ + DINNER + ch] * cw[ch * DCONV + k];
    }
    float s = acc / (1.f + __expf(-acc));
    xconv[(size_t)t * CONVDIM + ch] = s;
}

// ---------------- dt softplus ----------------
__global__ void dt_softplus_kernel(const float* __restrict__ zxbcdt,
                                   const float* __restrict__ dt_bias,
                                   float* __restrict__ dtout)
{
    int i = blockIdx.x * blockDim.x + threadIdx.x;
    if (i >= TTOT * NHEADS) return;
    int t = i >> 5;
    int h = i & 31;
    float v = zxbcdt[(size_t)t * DINPROJ + (DINPROJ - NHEADS) + h] + dt_bias[h];
    dtout[i] = (v > 20.f) ? v : log1pf(__expf(v));
}

// ---------------- SSD phase A: local chunk scans (zero initial state) --------
// grid: b*h*c = 2*32*16 = 1024 blocks. thread = (p, quad), quad owns 16 n's.
__global__ __launch_bounds__(256, 4)
void ssd_local_kernel(const float* __restrict__ xconv,
                      const float* __restrict__ dt,
                      const float* __restrict__ A_log,
                      const float* __restrict__ Dvec,
                      float* __restrict__ y,
                      float* __restrict__ Sloc,
                      float* __restrict__ cumdt)
{
    int bhc = blockIdx.x;
    int c = bhc & (NCH - 1);
    int h = (bhc >> 4) & 31;
    int b = bhc >> 9;
    float A  = -__expf(A_log[h]);
    float Dh = Dvec[h];
    int tid  = threadIdx.x;
    int p    = tid >> 2;
    int quad = tid & 3;
    int n0q  = quad * 16;

    __shared__ float sB[DSTATE], sC[DSTATE], sX[DHEAD];
    __shared__ float sdt;

    float s[16];
    #pragma unroll
    for (int j = 0; j < 16; j++) s[j] = 0.f;
    float cum = 0.f;
    int tbase = b * SEQ + c * CHL;

    for (int l = 0; l < CHL; l++) {
        int t = tbase + l;
        const float* row = xconv + (size_t)t * CONVDIM;
        if (tid < 64)        sB[tid]       = row[DINNER + tid];
        else if (tid < 128)  sC[tid - 64]  = row[DINNER + DSTATE + (tid - 64)];
        else if (tid < 192)  sX[tid - 128] = row[h * DHEAD + (tid - 128)];
        else if (tid == 192) sdt           = dt[(size_t)t * NHEADS + h];
        __syncthreads();

        float dts = sdt;
        cum += dts;
        if (tid == 0) cumdt[(size_t)t * NHEADS + h] = cum;
        float da = __expf(dts * A);
        float xp = sX[p] * dts;
        float accv = 0.f;
        #pragma unroll
        for (int j = 0; j < 16; j++) {
            s[j]  = fmaf(da, s[j], xp * sB[n0q + j]);
            accv  = fmaf(sC[n0q + j], s[j], accv);
        }
        accv += __shfl_xor_sync(0xffffffffu, accv, 1);
        accv += __shfl_xor_sync(0xffffffffu, accv, 2);
        if (quad == 0)
            y[(size_t)t * DINNER + h * DHEAD + p] = accv + Dh * sX[p];
        __syncthreads();
    }

    float* sl = Sloc + ((size_t)bhc * DHEAD + p) * DSTATE + n0q;
    #pragma unroll
    for (int j = 0; j < 16; j++) sl[j] = s[j];
}

// ---------------- SSD phase B: sequential carry combine over chunks ----------
// grid: 64 (b,h). 16 sequential steps.
__global__ void ssd_combine_kernel(const float* __restrict__ Sloc,
                                   const float* __restrict__ cumdt,
                                   const float* __restrict__ A_log,
                                   float* __restrict__ Sin)
{
    int bh = blockIdx.x;
    int b = bh >> 5, h = bh & 31;
    float A = -__expf(A_log[h]);
    int tid = threadIdx.x;
    int p = tid >> 2, quad = tid & 3, n0q = quad * 16;

    float s[16];
    #pragma unroll
    for (int j = 0; j < 16; j++) s[j] = 0.f;

    for (int c = 0; c < NCH; c++) {
        size_t base = (((size_t)(b * 512 + h * 16 + c)) * DHEAD + p) * DSTATE + n0q;
        float dec = __expf(A * cumdt[(size_t)(b * SEQ + c * CHL + CHL - 1) * NHEADS + h]);
        #pragma unroll
        for (int j = 0; j < 16; j++) {
            float sl = Sloc[base + j];
            Sin[base + j] = s[j];
            s[j] = fmaf(dec, s[j], sl);
        }
    }
}

// ---------------- SSD phase C: add cross-chunk contribution ------------------
// y_l += exp(A*cumdt_l) * (C_l . s_in)   per (b,h,c), c>0
__global__ __launch_bounds__(256, 4)
void ssd_correct_kernel(const float* __restrict__ xconv,
                        const float* __restrict__ cumdt,
                        const float* __restrict__ A_log,
                        const float* __restrict__ Sin,
                        float* __restrict__ y)
{
    int bhc = blockIdx.x;
    int c = bhc & (NCH - 1);
    if (c == 0) return;     // zero carry-in
    int h = (bhc >> 4) & 31;
    int b = bhc >> 9;
    float A = -__expf(A_log[h]);
    int tid = threadIdx.x;
    int p = tid >> 2, quad = tid & 3, n0q = quad * 16;

    float sin[16];
    {
        const float* sp = Sin + ((size_t)bhc * DHEAD + p) * DSTATE + n0q;
        #pragma unroll
        for (int j = 0; j < 16; j++) sin[j] = sp[j];
    }

    __shared__ float sC[DSTATE];
    __shared__ float scum;
    int tbase = b * SEQ + c * CHL;

    for (int l = 0; l < CHL; l++) {
        int t = tbase + l;
        if (tid < 64)       sC[tid] = xconv[(size_t)t * CONVDIM + DINNER + DSTATE + tid];
        else if (tid == 64) scum    = cumdt[(size_t)t * NHEADS + h];
        __syncthreads();
        float acc = 0.f;
        #pragma unroll
        for (int j = 0; j < 16; j++)
            acc = fmaf(sC[n0q + j], sin[j], acc);
        acc += __shfl_xor_sync(0xffffffffu, acc, 1);
        acc += __shfl_xor_sync(0xffffffffu, acc, 2);
        if (quad == 0) {
            float w = __expf(A * scum);
            y[(size_t)t * DINNER + h * DHEAD + p] += w * acc;
        }
        __syncthreads();
    }
}

// ---------------- gate (y * silu(z)) + rmsnorm(gnorm_w) ----------------
__global__ void gate_norm_kernel(const float* __restrict__ zxbcdt,
                                 const float* __restrict__ y,
                                 const float* __restrict__ gw,
                                 float* __restrict__ g)
{
    int t = blockIdx.x;
    __shared__ float sv[DINNER];
    __shared__ float wsum[8];
    const float* zr = zxbcdt + (size_t)t * DINPROJ;
    const float* yr = y + (size_t)t * DINNER;
    float lsum = 0.f;
    for (int i = threadIdx.x; i < DINNER; i += blockDim.x) {
        float z = zr[i];
        float v = yr[i] * (z / (1.f + __expf(-z)));
        sv[i] = v;
        lsum += v * v;
    }
    int lane = threadIdx.x & 31, wid = threadIdx.x >> 5;
    #pragma unroll
    for (int off = 16; off > 0; off >>= 1)
        lsum += __shfl_xor_sync(0xffffffffu, lsum, off);
    if (lane == 0) wsum[wid] = lsum;
    __syncthreads();
    __shared__ float s_rs;
    if (threadIdx.x == 0) {
        float tot = 0.f;
        for (int i = 0; i < 8; i++) tot += wsum[i];
        s_rs = rsqrtf(tot / (float)DINNER + EPSV);
    }
    __syncthreads();
    float rs = s_rs;
    float* grow = g + (size_t)t * DINNER;
    for (int i = threadIdx.x; i < DINNER; i += blockDim.x)
        grow[i] = sv[i] * rs * gw[i];
}

// ---------------- host orchestration ----------------
extern "C" void kernel_launch(void* const* d_in, const int* in_sizes, int n_in,
                              void* d_out, int out_size)
{
    const float* x        = (const float*)d_in[0];
    const float* in_w     = (const float*)d_in[1];  // (4, 4256, 1024)
    const float* conv_w   = (const float*)d_in[2];  // (4, 2176, 4)
    const float* conv_b   = (const float*)d_in[3];  // (4, 2176)
    const float* dt_bias  = (const float*)d_in[4];  // (4, 32)
    const float* A_log    = (const float*)d_in[5];  // (4, 32)
    const float* Dvec     = (const float*)d_in[6];  // (4, 32)
    const float* gnorm_w  = (const float*)d_in[7];  // (4, 2048)
    const float* out_w    = (const float*)d_in[8];  // (4, 1024, 2048)
    const float* rms_w    = (const float*)d_in[9];  // (4, 1024)
    float* out = (float*)d_out;

    float *p_xn, *p_zx, *p_xc, *p_dt, *p_y, *p_g, *p_sl, *p_si, *p_cd;
    __nv_bfloat16 *p_as, *p_bs;
    cudaGetSymbolAddress((void**)&p_xn, g_xn);
    cudaGetSymbolAddress((void**)&p_zx, g_zxbcdt);
    cudaGetSymbolAddress((void**)&p_xc, g_xconv);
    cudaGetSymbolAddress((void**)&p_dt, g_dt);
    cudaGetSymbolAddress((void**)&p_y,  g_y);
    cudaGetSymbolAddress((void**)&p_g,  g_g);
    cudaGetSymbolAddress((void**)&p_sl, g_Sloc);
    cudaGetSymbolAddress((void**)&p_si, g_Sin);
    cudaGetSymbolAddress((void**)&p_cd, g_cumdt);
    cudaGetSymbolAddress((void**)&p_as, g_asp);
    cudaGetSymbolAddress((void**)&p_bs, g_bsp);

    // residual stream lives in d_out
    cudaMemcpyAsync(out, x, (size_t)TTOT * DMODEL * sizeof(float),
                    cudaMemcpyDeviceToDevice);

    for (int layer = 0; layer < NLAYERS; layer++) {
        const float* lw_in   = in_w    + (size_t)layer * DINPROJ * DMODEL;
        const float* lw_cw   = conv_w  + (size_t)layer * CONVDIM * DCONV;
        const float* lw_cb   = conv_b  + (size_t)layer * CONVDIM;
        const float* lw_dtb  = dt_bias + (size_t)layer * NHEADS;
        const float* lw_Alog = A_log   + (size_t)layer * NHEADS;
        const float* lw_D    = Dvec    + (size_t)layer * NHEADS;
        const float* lw_gn   = gnorm_w + (size_t)layer * DINNER;
        const float* lw_out  = out_w   + (size_t)layer * DMODEL * DINNER;
        const float* lw_rms  = rms_w   + (size_t)layer * DMODEL;

        // 1. rmsnorm(x)
        rmsnorm_kernel<<<TTOT, 256>>>(out, lw_rms, p_xn, DMODEL);

        // 2. in_proj via split-bf16 tensor cores: zxbcdt = xn @ in_w^T
        split_kernel<<<(TTOT * DMODEL + 255) / 256, 256>>>(p_xn, p_as, TTOT, DMODEL, 0);
        split_kernel<<<(DINPROJ * DMODEL + 255) / 256, 256>>>(lw_in, p_bs, DINPROJ, DMODEL, 1);
        {
            dim3 grid((DINPROJ + BN - 1) / BN, TTOT / BM);
            gemm_bf16_nt<<<grid, 256>>>(p_as, p_bs, p_zx, TTOT, DINPROJ, 3 * DMODEL, 0);
        }

        // 3. conv + silu
        conv_silu_kernel<<<(TTOT * CONVDIM + 255) / 256, 256>>>(p_zx, lw_cw, lw_cb, p_xc);

        // 4. dt softplus
        dt_softplus_kernel<<<(TTOT * NHEADS + 255) / 256, 256>>>(p_zx, lw_dtb, p_dt);

        // 5. SSD: chunked 3-phase scan
        ssd_local_kernel<<<BATCH * NHEADS * NCH, 256>>>(p_xc, p_dt, lw_Alog, lw_D,
                                                        p_y, p_sl, p_cd);
        ssd_combine_kernel<<<BATCH * NHEADS, 256>>>(p_sl, p_cd, lw_Alog, p_si);
        ssd_correct_kernel<<<BATCH * NHEADS * NCH, 256>>>(p_xc, p_cd, lw_Alog, p_si, p_y);

        // 6. gate + group rmsnorm
        gate_norm_kernel<<<TTOT, 256>>>(p_zx, p_y, lw_gn, p_g);

        // 7. out_proj (split-bf16) with residual add into d_out
        split_kernel<<<(TTOT * DINNER + 255) / 256, 256>>>(p_g, p_as, TTOT, DINNER, 0);
        split_kernel<<<(DMODEL * DINNER + 255) / 256, 256>>>(lw_out, p_bs, DMODEL, DINNER, 1);
        {
            dim3 grid(DMODEL / BN, TTOT / BM);
            gemm_bf16_nt<<<grid, 256>>>(p_as, p_bs, out, TTOT, DMODEL, 3 * DINNER, 1);
        }
    }
}

// round 3
// speedup vs baseline: 3.1792x; 1.4644x over previous
#include <cuda_runtime.h>
#include <cuda_bf16.h>
#include <math.h>
#include <stdint.h>

// ---------------- problem constants ----------------
#define BATCH     2
#define SEQ       2048
#define TTOT      (BATCH*SEQ)        // 4096
#define DMODEL    1024
#define DINNER    2048
#define DHEAD     64
#define NHEADS    32
#define DSTATE    64
#define DCONV     4
#define CONVDIM   (DINNER + 2*DSTATE)            // 2176
#define DINPROJ   (2*DINNER + 2*DSTATE + NHEADS) // 4256
#define NLAYERS   4
#define EPSV      1e-5f

#define CHL       128                 // scan chunk length
#define NCH       (SEQ/CHL)           // 16 chunks per sequence
#define TT        8                   // scan timestep tile

// ---------------- scratch (device globals; no allocs allowed) ----------------
__device__ float g_zxbcdt[(size_t)TTOT * DINPROJ];  // in_proj output
__device__ float g_xconv[(size_t)TTOT * CONVDIM];   // silu(conv(xBC))
__device__ float g_dt[(size_t)TTOT * NHEADS];       // softplus(dt + bias)
__device__ float g_y[(size_t)TTOT * DINNER];        // SSD output (+ D*X)
// split-bf16 operand buffers
__device__ __nv_bfloat16 g_asp[(size_t)TTOT * 3 * DINNER];    // A triplets (max 4096x6144)
__device__ __nv_bfloat16 g_bsp[(size_t)DINPROJ * 3 * DMODEL]; // B triplets (max 4256x3072)
// chunked-scan buffers
__device__ float g_Sloc[(size_t)BATCH*NHEADS*NCH * DHEAD * DSTATE];
__device__ float g_Sin [(size_t)BATCH*NHEADS*NCH * DHEAD * DSTATE];
__device__ float g_cumdt[(size_t)TTOT * NHEADS];

// ---------------- rmsnorm + bf16 triplet split ([hi,lo,hi]) ----------------
__global__ void rmsnorm_split_kernel(const float* __restrict__ x,
                                     const float* __restrict__ w,
                                     __nv_bfloat16* __restrict__ O, int D)
{
    int t = blockIdx.x;
    const float* xr = x + (size_t)t * D;
    float lsum = 0.f;
    for (int i = threadIdx.x; i < D; i += blockDim.x) {
        float v = xr[i];
        lsum += v * v;
    }
    __shared__ float wsum[8];
    int lane = threadIdx.x & 31, wid = threadIdx.x >> 5;
    #pragma unroll
    for (int off = 16; off > 0; off >>= 1)
        lsum += __shfl_xor_sync(0xffffffffu, lsum, off);
    if (lane == 0) wsum[wid] = lsum;
    __syncthreads();
    __shared__ float s_rs;
    if (threadIdx.x == 0) {
        float tot = 0.f;
        int nw = blockDim.x >> 5;
        for (int i = 0; i < nw; i++) tot += wsum[i];
        s_rs = rsqrtf(tot / (float)D + EPSV);
    }
    __syncthreads();
    float rs = s_rs;
    __nv_bfloat16* orow = O + (size_t)t * (3 * D);
    for (int i = threadIdx.x; i < D; i += blockDim.x) {
        float v = xr[i] * rs * w[i];
        __nv_bfloat16 hi = __float2bfloat16(v);
        __nv_bfloat16 lo = __float2bfloat16(v - __bfloat162float(hi));
        orow[i]         = hi;
        orow[i + D]     = lo;
        orow[i + 2 * D] = hi;
    }
}

// ---------------- weight split: fp32 -> [hi, hi, lo] bf16 triplet ----------
__global__ void split_w_kernel(const float* __restrict__ X, __nv_bfloat16* __restrict__ O,
                               int rows, int K)
{
    int i = blockIdx.x * blockDim.x + threadIdx.x;
    if (i >= rows * K) return;
    int r = i / K, k = i % K;
    float x = X[i];
    __nv_bfloat16 hi = __float2bfloat16(x);
    __nv_bfloat16 lo = __float2bfloat16(x - __bfloat162float(hi));
    size_t base = (size_t)r * (3 * K) + k;
    O[base]         = hi;
    O[base + K]     = hi;
    O[base + 2 * K] = lo;
}

// ---------------- bf16 tensor-core NT GEMM, 3-stage cp.async pipeline --------
#define BM 128
#define BN 128
#define BK 32
#define PADH 8
#define SROW (BK + PADH)              // 40 elems
#define STAGE_ELEMS (128 * SROW)      // per operand per stage
#define GEMM_SMEM_BYTES (3 * 2 * STAGE_ELEMS * 2)

__device__ __forceinline__ void gemm_issue_tile(
    const __nv_bfloat16* __restrict__ A, const __nv_bfloat16* __restrict__ B,
    int N, int K, int m0, int n0, int kbase,
    __nv_bfloat16* As, __nv_bfloat16* Bs, int tid)
{
    #pragma unroll
    for (int it = 0; it < 2; it++) {
        int id  = tid + it * 256;       // 0..511
        int row = id >> 2;              // 0..127
        int col = (id & 3) * 8;         // 0,8,16,24
        {
            uint32_t saddr = (uint32_t)__cvta_generic_to_shared(&As[row * SROW + col]);
            const void* g = A + (size_t)(m0 + row) * K + kbase + col;
            asm volatile("cp.async.cg.shared.global [%0], [%1], 16;"
                         :: "r"(saddr), "l"(g));
        }
        {
            uint32_t saddr = (uint32_t)__cvta_generic_to_shared(&Bs[row * SROW + col]);
            int valid = (n0 + row) < N;
            const void* g = B + (valid ? ((size_t)(n0 + row) * K + kbase + col) : 0);
            int sz = valid ? 16 : 0;
            asm volatile("cp.async.cg.shared.global [%0], [%1], 16, %2;"
                         :: "r"(saddr), "l"(g), "r"(sz));
        }
    }
}

__global__ __launch_bounds__(256, 2)
void gemm_bf16_nt(const __nv_bfloat16* __restrict__ A, const __nv_bfloat16* __restrict__ B,
                  float* __restrict__ C, int M, int N, int K, int addC)
{
    extern __shared__ __align__(16) char dynsmem[];
    __nv_bfloat16* AsBase = (__nv_bfloat16*)dynsmem;                 // [3][128][SROW]
    __nv_bfloat16* BsBase = AsBase + 3 * STAGE_ELEMS;

    int tid  = threadIdx.x;
    int lane = tid & 31;
    int wid  = tid >> 5;
    int m0 = blockIdx.y * BM;
    int n0 = blockIdx.x * BN;
    int wm = (wid & 1) * 64;
    int wn = (wid >> 1) * 32;

    float acc[4][4][4];
    #pragma unroll
    for (int a = 0; a < 4; a++)
        #pragma unroll
        for (int b = 0; b < 4; b++)
            #pragma unroll
            for (int c = 0; c < 4; c++) acc[a][b][c] = 0.f;

    int NT = K / BK;

    // prologue: stages 0,1
    gemm_issue_tile(A, B, N, K, m0, n0, 0, AsBase, BsBase, tid);
    asm volatile("cp.async.commit_group;");
    if (NT > 1) {
        gemm_issue_tile(A, B, N, K, m0, n0, BK,
                        AsBase + STAGE_ELEMS, BsBase + STAGE_ELEMS, tid);
    }
    asm volatile("cp.async.commit_group;");

    for (int kt = 0; kt < NT; kt++) {
        asm volatile("cp.async.wait_group 1;");
        __syncthreads();
        // issue kt+2 into the stage freed by kt-1 (sync above guarantees done)
        if (kt + 2 < NT) {
            int st2 = (kt + 2) % 3;
            gemm_issue_tile(A, B, N, K, m0, n0, (kt + 2) * BK,
                            AsBase + st2 * STAGE_ELEMS, BsBase + st2 * STAGE_ELEMS, tid);
        }
        asm volatile("cp.async.commit_group;");

        __nv_bfloat16* As = AsBase + (kt % 3) * STAGE_ELEMS;
        __nv_bfloat16* Bs = BsBase + (kt % 3) * STAGE_ELEMS;

        #pragma unroll
        for (int ks = 0; ks < 2; ks++) {
            uint32_t af[4][4];
            uint32_t bf[4][2];
            #pragma unroll
            for (int mi = 0; mi < 4; mi++) {
                uint32_t addr = (uint32_t)__cvta_generic_to_shared(
                    &As[(wm + mi * 16 + (lane & 15)) * SROW + ks * 16 + (lane >> 4) * 8]);
                asm volatile("ldmatrix.sync.aligned.m8n8.x4.shared.b16 {%0,%1,%2,%3}, [%4];"
                             : "=r"(af[mi][0]), "=r"(af[mi][1]),
                               "=r"(af[mi][2]), "=r"(af[mi][3])
                             : "r"(addr));
            }
            #pragma unroll
            for (int nj = 0; nj < 4; nj += 2) {
                uint32_t addr = (uint32_t)__cvta_generic_to_shared(
                    &Bs[(wn + nj * 8 + (lane >> 4) * 8 + (lane & 7)) * SROW
                        + ks * 16 + ((lane >> 3) & 1) * 8]);
                asm volatile("ldmatrix.sync.aligned.m8n8.x4.shared.b16 {%0,%1,%2,%3}, [%4];"
                             : "=r"(bf[nj][0]), "=r"(bf[nj][1]),
                               "=r"(bf[nj + 1][0]), "=r"(bf[nj + 1][1])
                             : "r"(addr));
            }
            #pragma unroll
            for (int mi = 0; mi < 4; mi++)
                #pragma unroll
                for (int nj = 0; nj < 4; nj++)
                    asm volatile(
                        "mma.sync.aligned.m16n8k16.row.col.f32.bf16.bf16.f32 "
                        "{%0,%1,%2,%3}, {%4,%5,%6,%7}, {%8,%9}, {%0,%1,%2,%3};"
                        : "+f"(acc[mi][nj][0]), "+f"(acc[mi][nj][1]),
                          "+f"(acc[mi][nj][2]), "+f"(acc[mi][nj][3])
                        : "r"(af[mi][0]), "r"(af[mi][1]),
                          "r"(af[mi][2]), "r"(af[mi][3]),
                          "r"(bf[nj][0]), "r"(bf[nj][1]));
        }
        __syncthreads();
    }

    #pragma unroll
    for (int mi = 0; mi < 4; mi++) {
        int r0 = m0 + wm + mi * 16 + (lane >> 2);
        #pragma unroll
        for (int nj = 0; nj < 4; nj++) {
            int c0 = n0 + wn + nj * 8 + (lane & 3) * 2;
            if (c0 < N) {
                float* p0 = C + (size_t)r0 * N + c0;
                float* p1 = C + (size_t)(r0 + 8) * N + c0;
                if (addC) {
                    p0[0] += acc[mi][nj][0];  p0[1] += acc[mi][nj][1];
                    p1[0] += acc[mi][nj][2];  p1[1] += acc[mi][nj][3];
                } else {
                    p0[0] = acc[mi][nj][0];   p0[1] = acc[mi][nj][1];
                    p1[0] = acc[mi][nj][2];   p1[1] = acc[mi][nj][3];
                }
            }
        }
    }
}

// ---------------- depthwise conv(4) + silu ----------------
__global__ void conv_silu_kernel(const float* __restrict__ zxbcdt,
                                 const float* __restrict__ cw,
                                 const float* __restrict__ cb,
                                 float* __restrict__ xconv)
{
    int idx = blockIdx.x * blockDim.x + threadIdx.x;
    if (idx >= TTOT * CONVDIM) return;
    int ch = idx % CONVDIM;
    int t  = idx / CONVDIM;
    int l  = t & (SEQ - 1);
    int b  = t >> 11;
    float acc = cb[ch];
    #pragma unroll
    for (int k = 0; k < DCONV; k++) {
        int ll = l + k - (DCONV - 1);
        if (ll >= 0)
            acc += zxbcdt[((size_t)(b * SEQ + ll)) * DINPROJ + DINNER + ch] * cw[ch * DCONV + k];
    }
    float s = acc / (1.f + __expf(-acc));
    xconv[(size_t)t * CONVDIM + ch] = s;
}

// ---------------- dt softplus ----------------
__global__ void dt_softplus_kernel(const float* __restrict__ zxbcdt,
                                   const float* __restrict__ dt_bias,
                                   float* __restrict__ dtout)
{
    int i = blockIdx.x * blockDim.x + threadIdx.x;
    if (i >= TTOT * NHEADS) return;
    int t = i >> 5;
    int h = i & 31;
    float v = zxbcdt[(size_t)t * DINPROJ + (DINPROJ - NHEADS) + h] + dt_bias[h];
    dtout[i] = (v > 20.f) ? v : log1pf(__expf(v));
}

// ---------------- SSD phase A: local chunk scans, 8-step tiles ---------------
// thread = (p, quad); quad owns n = quad + 4*j, j=0..15 (bank-conflict-free).
__global__ __launch_bounds__(256, 4)
void ssd_local_kernel(const float* __restrict__ xconv,
                      const float* __restrict__ dt,
                      const float* __restrict__ A_log,
                      const float* __restrict__ Dvec,
                      float* __restrict__ y,
                      float* __restrict__ Sloc,
                      float* __restrict__ cumdt)
{
    int bhc = blockIdx.x;
    int c = bhc & (NCH - 1);
    int h = (bhc >> 4) & 31;
    int b = bhc >> 9;
    float A  = -__expf(A_log[h]);
    float Dh = Dvec[h];
    int tid  = threadIdx.x;
    int p    = tid >> 2;
    int quad = tid & 3;

    __shared__ float sB[TT][DSTATE], sC[TT][DSTATE], sX[TT][DHEAD];
    __shared__ float sdt[TT];

    float s[16];
    #pragma unroll
    for (int j = 0; j < 16; j++) s[j] = 0.f;
    float cum = 0.f;
    int tbase = b * SEQ + c * CHL;

    for (int t0 = 0; t0 < CHL; t0 += TT) {
        for (int idx = tid; idx < TT * 192; idx += 256) {
            int w = idx / 192, r = idx - w * 192;
            const float* row = xconv + (size_t)(tbase + t0 + w) * CONVDIM;
            if (r < 64)        sB[w][r]       = row[DINNER + r];
            else if (r < 128)  sC[w][r - 64]  = row[DINNER + DSTATE + (r - 64)];
            else               sX[w][r - 128] = row[h * DHEAD + (r - 128)];
        }
        if (tid < TT) sdt[tid] = dt[(size_t)(tbase + t0 + tid) * NHEADS + h];
        __syncthreads();

        if (tid == 0) {
            float cc = cum;
            #pragma unroll
            for (int w = 0; w < TT; w++) {
                cc += sdt[w];
                cumdt[(size_t)(tbase + t0 + w) * NHEADS + h] = cc;
            }
            cum = cc;
        }

        #pragma unroll
        for (int w = 0; w < TT; w++) {
            float dts = sdt[w];
            float da  = __expf(dts * A);
            float xp  = sX[w][p] * dts;
            float accv = 0.f;
            #pragma unroll
            for (int j = 0; j < 16; j++) {
                float bv = sB[w][quad + 4 * j];
                s[j]  = fmaf(da, s[j], xp * bv);
                accv  = fmaf(sC[w][quad + 4 * j], s[j], accv);
            }
            accv += __shfl_xor_sync(0xffffffffu, accv, 1);
            accv += __shfl_xor_sync(0xffffffffu, accv, 2);
            if (quad == 0)
                y[(size_t)(tbase + t0 + w) * DINNER + h * DHEAD + p] = accv + Dh * sX[w][p];
        }
        __syncthreads();
    }

    float* sl = Sloc + ((size_t)bhc * DHEAD + p) * DSTATE + quad;
    #pragma unroll
    for (int j = 0; j < 16; j++) sl[4 * j] = s[j];
}

// ---------------- SSD phase B: sequential carry combine over chunks ----------
__global__ void ssd_combine_kernel(const float* __restrict__ Sloc,
                                   const float* __restrict__ cumdt,
                                   const float* __restrict__ A_log,
                                   float* __restrict__ Sin)
{
    int bh = blockIdx.x;
    int b = bh >> 5, h = bh & 31;
    float A = -__expf(A_log[h]);
    int tid = threadIdx.x;
    int p = tid >> 2, quad = tid & 3;

    float s[16];
    #pragma unroll
    for (int j = 0; j < 16; j++) s[j] = 0.f;

    for (int c = 0; c < NCH; c++) {
        size_t base = (((size_t)(b * 512 + h * 16 + c)) * DHEAD + p) * DSTATE + quad;
        float dec = __expf(A * cumdt[(size_t)(b * SEQ + c * CHL + CHL - 1) * NHEADS + h]);
        #pragma unroll
        for (int j = 0; j < 16; j++) {
            float sl = Sloc[base + 4 * j];
            Sin[base + 4 * j] = s[j];
            s[j] = fmaf(dec, s[j], sl);
        }
    }
}

// ---------------- SSD phase C: cross-chunk correction, 8-step tiles ----------
__global__ __launch_bounds__(256, 4)
void ssd_correct_kernel(const float* __restrict__ xconv,
                        const float* __restrict__ cumdt,
                        const float* __restrict__ A_log,
                        const float* __restrict__ Sin,
                        float* __restrict__ y)
{
    int bhc = blockIdx.x;
    int c = bhc & (NCH - 1);
    if (c == 0) return;
    int h = (bhc >> 4) & 31;
    int b = bhc >> 9;
    float A = -__expf(A_log[h]);
    int tid = threadIdx.x;
    int p = tid >> 2, quad = tid & 3;

    float sin[16];
    {
        const float* sp = Sin + ((size_t)bhc * DHEAD + p) * DSTATE + quad;
        #pragma unroll
        for (int j = 0; j < 16; j++) sin[j] = sp[4 * j];
    }

    __shared__ float sC[TT][DSTATE];
    __shared__ float scum[TT];
    int tbase = b * SEQ + c * CHL;

    for (int t0 = 0; t0 < CHL; t0 += TT) {
        for (int idx = tid; idx < TT * 64; idx += 256) {
            int w = idx >> 6, r = idx & 63;
            sC[w][r] = xconv[(size_t)(tbase + t0 + w) * CONVDIM + DINNER + DSTATE + r];
        }
        if (tid < TT) scum[tid] = cumdt[(size_t)(tbase + t0 + tid) * NHEADS + h];
        __syncthreads();

        #pragma unroll
        for (int w = 0; w < TT; w++) {
            float acc = 0.f;
            #pragma unroll
            for (int j = 0; j < 16; j++)
                acc = fmaf(sC[w][quad + 4 * j], sin[j], acc);
            acc += __shfl_xor_sync(0xffffffffu, acc, 1);
            acc += __shfl_xor_sync(0xffffffffu, acc, 2);
            if (quad == 0) {
                float wgt = __expf(A * scum[w]);
                y[(size_t)(tbase + t0 + w) * DINNER + h * DHEAD + p] += wgt * acc;
            }
        }
        __syncthreads();
    }
}

// ---------------- gate (y * silu(z)) + rmsnorm + bf16 triplet split ----------
__global__ void gate_norm_split_kernel(const float* __restrict__ zxbcdt,
                                       const float* __restrict__ y,
                                       const float* __restrict__ gw,
                                       __nv_bfloat16* __restrict__ O)
{
    int t = blockIdx.x;
    __shared__ float sv[DINNER];
    __shared__ float wsum[8];
    const float* zr = zxbcdt + (size_t)t * DINPROJ;
    const float* yr = y + (size_t)t * DINNER;
    float lsum = 0.f;
    for (int i = threadIdx.x; i < DINNER; i += blockDim.x) {
        float z = zr[i];
        float v = yr[i] * (z / (1.f + __expf(-z)));
        sv[i] = v;
        lsum += v * v;
    }
    int lane = threadIdx.x & 31, wid = threadIdx.x >> 5;
    #pragma unroll
    for (int off = 16; off > 0; off >>= 1)
        lsum += __shfl_xor_sync(0xffffffffu, lsum, off);
    if (lane == 0) wsum[wid] = lsum;
    __syncthreads();
    __shared__ float s_rs;
    if (threadIdx.x == 0) {
        float tot = 0.f;
        for (int i = 0; i < 8; i++) tot += wsum[i];
        s_rs = rsqrtf(tot / (float)DINNER + EPSV);
    }
    __syncthreads();
    float rs = s_rs;
    __nv_bfloat16* orow = O + (size_t)t * (3 * DINNER);
    for (int i = threadIdx.x; i < DINNER; i += blockDim.x) {
        float v = sv[i] * rs * gw[i];
        __nv_bfloat16 hi = __float2bfloat16(v);
        __nv_bfloat16 lo = __float2bfloat16(v - __bfloat162float(hi));
        orow[i]              = hi;
        orow[i + DINNER]     = lo;
        orow[i + 2 * DINNER] = hi;
    }
}

// ---------------- host orchestration ----------------
extern "C" void kernel_launch(void* const* d_in, const int* in_sizes, int n_in,
                              void* d_out, int out_size)
{
    const float* x        = (const float*)d_in[0];
    const float* in_w     = (const float*)d_in[1];
    const float* conv_w   = (const float*)d_in[2];
    const float* conv_b   = (const float*)d_in[3];
    const float* dt_bias  = (const float*)d_in[4];
    const float* A_log    = (const float*)d_in[5];
    const float* Dvec     = (const float*)d_in[6];
    const float* gnorm_w  = (const float*)d_in[7];
    const float* out_w    = (const float*)d_in[8];
    const float* rms_w    = (const float*)d_in[9];
    float* out = (float*)d_out;

    float *p_zx, *p_xc, *p_dt, *p_y, *p_sl, *p_si, *p_cd;
    __nv_bfloat16 *p_as, *p_bs;
    cudaGetSymbolAddress((void**)&p_zx, g_zxbcdt);
    cudaGetSymbolAddress((void**)&p_xc, g_xconv);
    cudaGetSymbolAddress((void**)&p_dt, g_dt);
    cudaGetSymbolAddress((void**)&p_y,  g_y);
    cudaGetSymbolAddress((void**)&p_sl, g_Sloc);
    cudaGetSymbolAddress((void**)&p_si, g_Sin);
    cudaGetSymbolAddress((void**)&p_cd, g_cumdt);
    cudaGetSymbolAddress((void**)&p_as, g_asp);
    cudaGetSymbolAddress((void**)&p_bs, g_bsp);

    cudaFuncSetAttribute(gemm_bf16_nt,
                         cudaFuncAttributeMaxDynamicSharedMemorySize, GEMM_SMEM_BYTES);

    cudaMemcpyAsync(out, x, (size_t)TTOT * DMODEL * sizeof(float),
                    cudaMemcpyDeviceToDevice);

    for (int layer = 0; layer < NLAYERS; layer++) {
        const float* lw_in   = in_w    + (size_t)layer * DINPROJ * DMODEL;
        const float* lw_cw   = conv_w  + (size_t)layer * CONVDIM * DCONV;
        const float* lw_cb   = conv_b  + (size_t)layer * CONVDIM;
        const float* lw_dtb  = dt_bias + (size_t)layer * NHEADS;
        const float* lw_Alog = A_log   + (size_t)layer * NHEADS;
        const float* lw_D    = Dvec    + (size_t)layer * NHEADS;
        const float* lw_gn   = gnorm_w + (size_t)layer * DINNER;
        const float* lw_out  = out_w   + (size_t)layer * DMODEL * DINNER;
        const float* lw_rms  = rms_w   + (size_t)layer * DMODEL;

        // 1. rmsnorm(x) -> bf16 triplet A operand
        rmsnorm_split_kernel<<<TTOT, 256>>>(out, lw_rms, p_as, DMODEL);

        // 2. in_proj
        split_w_kernel<<<(DINPROJ * DMODEL + 255) / 256, 256>>>(lw_in, p_bs, DINPROJ, DMODEL);
        {
            dim3 grid((DINPROJ + BN - 1) / BN, TTOT / BM);
            gemm_bf16_nt<<<grid, 256, GEMM_SMEM_BYTES>>>(p_as, p_bs, p_zx,
                                                         TTOT, DINPROJ, 3 * DMODEL, 0);
        }

        // 3. conv + silu
        conv_silu_kernel<<<(TTOT * CONVDIM + 255) / 256, 256>>>(p_zx, lw_cw, lw_cb, p_xc);

        // 4. dt softplus
        dt_softplus_kernel<<<(TTOT * NHEADS + 255) / 256, 256>>>(p_zx, lw_dtb, p_dt);

        // 5. SSD: chunked 3-phase scan
        ssd_local_kernel<<<BATCH * NHEADS * NCH, 256>>>(p_xc, p_dt, lw_Alog, lw_D,
                                                        p_y, p_sl, p_cd);
        ssd_combine_kernel<<<BATCH * NHEADS, 256>>>(p_sl, p_cd, lw_Alog, p_si);
        ssd_correct_kernel<<<BATCH * NHEADS * NCH, 256>>>(p_xc, p_cd, lw_Alog, p_si, p_y);

        // 6. gate + rmsnorm -> bf16 triplet A operand
        gate_norm_split_kernel<<<TTOT, 256>>>(p_zx, p_y, lw_gn, p_as);

        // 7. out_proj with residual add
        split_w_kernel<<<(DMODEL * DINNER + 255) / 256, 256>>>(lw_out, p_bs, DMODEL, DINNER);
        {
            dim3 grid(DMODEL / BN, TTOT / BM);
            gemm_bf16_nt<<<grid, 256, GEMM_SMEM_BYTES>>>(p_as, p_bs, out,
                                                         TTOT, DMODEL, 3 * DINNER, 1);
        }
    }
}